// round 3
// baseline (speedup 1.0000x reference)
#include <cuda_runtime.h>
#include <cstdint>

// Problem constants (fixed shapes from the reference)
constexpr int T = 8;
constexpr int N = 200000;
constexpr int D = 128;        // embedding dim (fp32) -> 512 bytes/row
constexpr int B = 8192;       // bags per table (power of 2)
constexpr int L = 163840;     // indices per table
constexpr int D4 = D / 4;     // 32 float4 per row; one per lane
constexpr int UNROLL = 8;     // independent row gathers in flight per warp
constexpr int TOTAL_BAGS = T * B;       // 65536
constexpr int BAGS_PER_GRAB = 8;        // bags per atomic counter grab

// Work-stealing counter (device global: no allocation allowed).
__device__ unsigned int g_bag_counter;

__global__ void reset_counter_kernel() { g_bag_counter = 0u; }

// Persistent-ish kernel: one wave of blocks; each warp repeatedly grabs a
// batch of BAGS_PER_GRAB consecutive (table, bag) pairs and sum-pools them.
// lane l owns out columns [l*4, l*4+4) of the D=128 segment of each bag.
__global__ __launch_bounds__(256)
void grouped_embedding_bag_kernel(const float* __restrict__ weights,   // [T, N, D]
                                  const int*   __restrict__ values,    // [T, L]
                                  const int*   __restrict__ offsets,   // [T, B+1]
                                  float*       __restrict__ out)       // [B, T*D]
{
    const int lane = threadIdx.x & 31;
    float4* __restrict__ out4 = reinterpret_cast<float4*>(out);

    while (true) {
        // One lane grabs a batch of bags; broadcast to the warp.
        unsigned int base;
        if (lane == 0) base = atomicAdd(&g_bag_counter, (unsigned)BAGS_PER_GRAB);
        base = __shfl_sync(0xffffffffu, base, 0);
        if (base >= (unsigned)TOTAL_BAGS) return;

        const unsigned int limit = min(base + (unsigned)BAGS_PER_GRAB,
                                       (unsigned)TOTAL_BAGS);

        for (unsigned int g = base; g < limit; ++g) {
            const int t = (int)(g >> 13);          // / B  (B = 8192 = 2^13)
            const int b = (int)(g & (B - 1));      // % B

            const int start = offsets[t * (B + 1) + b];
            const int end   = offsets[t * (B + 1) + b + 1];

            const float4* __restrict__ wt =
                reinterpret_cast<const float4*>(weights) + (size_t)t * N * D4;
            const int* __restrict__ vals = values + (size_t)t * L;

            float acc0 = 0.f, acc1 = 0.f, acc2 = 0.f, acc3 = 0.f;

            for (int i = start; i < end; i += UNROLL) {
                // Batch 1: all index loads issued together (uniform broadcast).
                int idx[UNROLL];
                #pragma unroll
                for (int j = 0; j < UNROLL; ++j) {
                    idx[j] = (i + j < end) ? vals[i + j] : -1;
                }
                // Batch 2: all row loads issued together (MLP=UNROLL).
                float4 v[UNROLL];
                #pragma unroll
                for (int j = 0; j < UNROLL; ++j) {
                    if (idx[j] >= 0) {
                        v[j] = wt[(size_t)idx[j] * D4 + lane];
                    } else {
                        v[j] = make_float4(0.f, 0.f, 0.f, 0.f);
                    }
                }
                #pragma unroll
                for (int j = 0; j < UNROLL; ++j) {
                    acc0 += v[j].x;
                    acc1 += v[j].y;
                    acc2 += v[j].z;
                    acc3 += v[j].w;
                }
            }

            // out[b, t*D + lane*4 .. +4)
            out4[(size_t)b * (T * D4) + t * D4 + lane] =
                make_float4(acc0, acc1, acc2, acc3);
        }
    }
}

extern "C" void kernel_launch(void* const* d_in, const int* in_sizes, int n_in,
                              void* d_out, int out_size)
{
    const float* weights = (const float*)d_in[0];   // [T, N, D] fp32
    const int*   values  = (const int*)d_in[1];     // [T, L] int32
    const int*   offsets = (const int*)d_in[2];     // [T, B+1] int32
    float*       out     = (float*)d_out;           // [B, T*D] fp32

    // Reset the work-stealing counter (graph-capturable: plain kernel launch).
    reset_counter_kernel<<<1, 1>>>();

    // One full wave: 8 blocks/SM x 256 threads = 2048 threads/SM.
    // 152 SMs on GB300 -> 1216 blocks. Extra blocks would just drain and exit.
    const int threads = 256;
    const int blocks  = 152 * 8;

    grouped_embedding_bag_kernel<<<blocks, threads>>>(weights, values, offsets, out);
}

// round 4
// speedup vs baseline: 1.2475x; 1.2475x over previous
#include <cuda_runtime.h>
#include <cstdint>

// Problem constants (fixed shapes from the reference)
constexpr int T = 8;
constexpr int N = 200000;
constexpr int D = 128;        // embedding dim (fp32) -> 512 bytes/row
constexpr int B = 8192;       // bags per table (power of 2)
constexpr int L = 163840;     // indices per table
constexpr int D4 = D / 4;     // 32 float4 per row; one per lane
constexpr int UNROLL = 8;     // independent row gathers in flight per warp

// One warp handles one (table, bag) pair; 2 warps per CTA so the CTA slot is
// released at max-of-2 bag lengths (1.5x mean) instead of max-of-8 (2.7x mean).
// Static contiguous bag order keeps the machine's active window inside ~one
// table at a time -> best L2 duplicate-row hit rate (traffic is the binding
// constraint: DRAM gather pattern ceiling ~4.5 TB/s measured R1-R3).
__global__ __launch_bounds__(64)
void grouped_embedding_bag_kernel(const float* __restrict__ weights,   // [T, N, D]
                                  const int*   __restrict__ values,    // [T, L]
                                  const int*   __restrict__ offsets,   // [T, B+1]
                                  float*       __restrict__ out)       // [B, T*D]
{
    const int warp_global = (blockIdx.x * blockDim.x + threadIdx.x) >> 5;
    const int lane = threadIdx.x & 31;
    if (warp_global >= T * B) return;

    const int t = warp_global >> 13;        // / B  (B = 8192 = 2^13)
    const int b = warp_global & (B - 1);    // % B

    const int start = __ldg(&offsets[t * (B + 1) + b]);
    const int end   = __ldg(&offsets[t * (B + 1) + b + 1]);

    const float4* __restrict__ wt =
        reinterpret_cast<const float4*>(weights) + (size_t)t * N * D4;
    const int* __restrict__ vals = values + (size_t)t * L;

    float acc0 = 0.f, acc1 = 0.f, acc2 = 0.f, acc3 = 0.f;

    for (int i = start; i < end; i += UNROLL) {
        // Batch 1: all index loads issued together (warp-uniform broadcast).
        int idx[UNROLL];
        #pragma unroll
        for (int j = 0; j < UNROLL; ++j) {
            idx[j] = (i + j < end) ? __ldg(&vals[i + j]) : -1;
        }
        // Batch 2: all row loads issued together (MLP=UNROLL).
        float4 v[UNROLL];
        #pragma unroll
        for (int j = 0; j < UNROLL; ++j) {
            if (idx[j] >= 0) {
                v[j] = wt[(size_t)idx[j] * D4 + lane];
            } else {
                v[j] = make_float4(0.f, 0.f, 0.f, 0.f);
            }
        }
        #pragma unroll
        for (int j = 0; j < UNROLL; ++j) {
            acc0 += v[j].x;
            acc1 += v[j].y;
            acc2 += v[j].z;
            acc3 += v[j].w;
        }
    }

    // out[b, t*D + lane*4 .. +4)  — streaming store (evict-first): the output
    // is never re-read, keep L2 capacity for embedding rows.
    float4 result = make_float4(acc0, acc1, acc2, acc3);
    float4* out4 = reinterpret_cast<float4*>(out) +
                   (size_t)b * (T * D4) + t * D4 + lane;
    __stcs(out4, result);
}

extern "C" void kernel_launch(void* const* d_in, const int* in_sizes, int n_in,
                              void* d_out, int out_size)
{
    const float* weights = (const float*)d_in[0];   // [T, N, D] fp32
    const int*   values  = (const int*)d_in[1];     // [T, L] int32
    const int*   offsets = (const int*)d_in[2];     // [T, B+1] int32
    float*       out     = (float*)d_out;           // [B, T*D] fp32

    const int total_warps   = T * B;                // 65536
    const int threads       = 64;                   // 2 warps/block
    const int warps_per_blk = threads / 32;
    const int blocks        = (total_warps + warps_per_blk - 1) / warps_per_blk;

    grouped_embedding_bag_kernel<<<blocks, threads>>>(weights, values, offsets, out);
}

// round 5
// speedup vs baseline: 1.4457x; 1.1589x over previous
#include <cuda_runtime.h>
#include <cstdint>

// Problem constants (fixed shapes from the reference)
constexpr int T = 8;
constexpr int N = 200000;
constexpr int D = 128;        // embedding dim (fp32) -> 512 bytes/row
constexpr int B = 8192;       // bags per table (power of 2)
constexpr int L = 163840;     // indices per table
constexpr int D4 = D / 4;     // 32 float4 per row; one per lane
constexpr int UNROLL = 8;     // rows in flight per warp (cp.async depth)
constexpr int WARPS_PER_CTA = 2;

__device__ __forceinline__ uint32_t smem_u32(const void* p) {
    uint32_t a;
    asm("{ .reg .u64 t; cvta.to.shared.u64 t, %1; cvt.u32.u64 %0, t; }"
        : "=r"(a) : "l"(p));
    return a;
}

// Predicated 16-byte async copy gmem -> smem (no register destination:
// this is what lets MLP=8 coexist with ~30 regs/thread).
__device__ __forceinline__ void cp_async16(uint32_t saddr, const void* gptr, int pred) {
    asm volatile(
        "{\n\t"
        ".reg .pred p;\n\t"
        "setp.ne.u32 p, %2, 0;\n\t"
        "@p cp.async.cg.shared.global [%0], [%1], 16;\n\t"
        "}"
        :: "r"(saddr), "l"(gptr), "r"((unsigned)pred) : "memory");
}

// One warp per (table, bag). Rows staged through smem via cp.async; each lane
// writes and reads back only its own 16B slice (no cross-thread smem traffic).
// Next batch's indices are prefetched behind the cp.async wait.
__global__ __launch_bounds__(WARPS_PER_CTA * 32)
void grouped_embedding_bag_kernel(const float* __restrict__ weights,   // [T, N, D]
                                  const int*   __restrict__ values,    // [T, L]
                                  const int*   __restrict__ offsets,   // [T, B+1]
                                  float*       __restrict__ out)       // [B, T*D]
{
    __shared__ float4 buf[WARPS_PER_CTA][UNROLL][32];   // 8 KB per CTA

    const int warp_global = (blockIdx.x * blockDim.x + threadIdx.x) >> 5;
    const int lane    = threadIdx.x & 31;
    const int warp_in = (threadIdx.x >> 5);
    if (warp_global >= T * B) return;

    const int t = warp_global >> 13;        // / B  (B = 8192 = 2^13)
    const int b = warp_global & (B - 1);    // % B

    const int start = __ldg(&offsets[t * (B + 1) + b]);
    const int end   = __ldg(&offsets[t * (B + 1) + b + 1]);

    const float4* __restrict__ wt =
        reinterpret_cast<const float4*>(weights) + (size_t)t * N * D4;
    const int* __restrict__ vals = values + (size_t)t * L;

    float acc0 = 0.f, acc1 = 0.f, acc2 = 0.f, acc3 = 0.f;

    // My lane's smem slots (one float4 per row slot).
    uint32_t s_base = smem_u32(&buf[warp_in][0][lane]);

    // Prime: indices for the first batch.
    int idx[UNROLL];
    #pragma unroll
    for (int j = 0; j < UNROLL; ++j)
        idx[j] = (start + j < end) ? __ldg(&vals[start + j]) : -1;

    for (int i = start; i < end; i += UNROLL) {
        // Issue the 8 row gathers for this batch (predicated on validity).
        #pragma unroll
        for (int j = 0; j < UNROLL; ++j) {
            const float4* g = wt + (size_t)(idx[j] < 0 ? 0 : idx[j]) * D4 + lane;
            cp_async16(s_base + (uint32_t)(j * 32 * sizeof(float4)), g, idx[j] >= 0);
        }
        asm volatile("cp.async.commit_group;" ::: "memory");

        // Prefetch next batch's indices while the copies are in flight.
        const int ni = i + UNROLL;
        int nidx[UNROLL];
        #pragma unroll
        for (int j = 0; j < UNROLL; ++j)
            nidx[j] = (ni + j < end) ? __ldg(&vals[ni + j]) : -1;

        asm volatile("cp.async.wait_group 0;" ::: "memory");

        // Accumulate this batch (self-written smem: no syncwarp needed).
        #pragma unroll
        for (int j = 0; j < UNROLL; ++j) {
            if (idx[j] >= 0) {
                float4 v = buf[warp_in][j][lane];
                acc0 += v.x; acc1 += v.y; acc2 += v.z; acc3 += v.w;
            }
        }

        #pragma unroll
        for (int j = 0; j < UNROLL; ++j) idx[j] = nidx[j];
    }

    // out[b, t*D + lane*4 .. +4) — streaming store, output is never re-read.
    float4 result = make_float4(acc0, acc1, acc2, acc3);
    float4* out4 = reinterpret_cast<float4*>(out) +
                   (size_t)b * (T * D4) + t * D4 + lane;
    __stcs(out4, result);
}

extern "C" void kernel_launch(void* const* d_in, const int* in_sizes, int n_in,
                              void* d_out, int out_size)
{
    const float* weights = (const float*)d_in[0];   // [T, N, D] fp32
    const int*   values  = (const int*)d_in[1];     // [T, L] int32
    const int*   offsets = (const int*)d_in[2];     // [T, B+1] int32
    float*       out     = (float*)d_out;           // [B, T*D] fp32

    const int total_warps = T * B;                  // 65536
    const int threads     = WARPS_PER_CTA * 32;     // 64
    const int blocks      = total_warps / WARPS_PER_CTA;

    grouped_embedding_bag_kernel<<<blocks, threads>>>(weights, values, offsets, out);
}